// round 15
// baseline (speedup 1.0000x reference)
#include <cuda_runtime.h>
#include <cuda_fp16.h>
#include <cstdint>

// Router: logits = x@W + b (N=16384, D=2048, E=64), softmax, top-2, aux loss.
// fp16 m16n8k16 mma 3-pass (rn hi/lo split, residual scaled 2^12).
// Warp grid 8x1; B pre-split into u32 BH/BL smem tiles at stage time.
// Split accumulators + per-chunk drain of hh into FFMA fp32 sums.
// Finalize folded into main kernel (last-block threadfence reduction).
// Output layout (float32): [weights N*2][indices-as-float N*2][aux 1]

#define DDIM   2048
#define EDIM   64
#define BM     128
#define BK     32
#define NCHUNK (DDIM / BK)      // 64
#define NTHREADS 256

#define ASTRIDE 36              // floats per A row
#define BPITCH  72              // u32 per B pair-row: banks 8tg+g, conflict-free

// smem layout
#define A_OFF     0                          // floats: 128 x 36 = 4608
#define BH_U      4608                       // u32: 16 pairs x 72 = 1152
#define BL_U      5760                       // u32: 1152 -> ends 6912
#define LG_OFF    0                          // reuse: 128 x 65 = 8320 floats
#define LG_STRIDE 65
#define BIAS_OFF  8320                       // 64 floats (reused as reduce buf)
#define CNT_OFF   8384                       // 64 ints
#define SMEM_FLOATS 8448                     // 33792 bytes

#define RSCALE   4096.0f
#define RSCALE_I (1.0f / 4096.0f)

__device__ float g_cnt[EDIM];
__device__ float g_prob[EDIM];
__device__ unsigned g_done;

__global__ void zero_acc_kernel() {
    int t = threadIdx.x;
    if (t < EDIM) { g_cnt[t] = 0.0f; g_prob[t] = 0.0f; }
    if (t == 0) g_done = 0u;
}

__device__ __forceinline__ void mma16h(float d[4],
                                       uint32_t a0, uint32_t a1, uint32_t a2, uint32_t a3,
                                       uint32_t b0, uint32_t b1) {
    asm volatile(
        "mma.sync.aligned.m16n8k16.row.col.f32.f16.f16.f32 "
        "{%0,%1,%2,%3}, {%4,%5,%6,%7}, {%8,%9}, {%0,%1,%2,%3};"
        : "+f"(d[0]), "+f"(d[1]), "+f"(d[2]), "+f"(d[3])
        : "r"(a0), "r"(a1), "r"(a2), "r"(a3), "r"(b0), "r"(b1));
}

// (v0,v1) -> hi f16x2 (rn; low half = v0) and scaled-residual f16x2.
__device__ __forceinline__ void prep2(float v0, float v1, uint32_t& hi, uint32_t& lo) {
    __half h0 = __float2half_rn(v0);
    __half h1 = __float2half_rn(v1);
    __half2 hp = __halves2half2(h0, h1);
    hi = *reinterpret_cast<uint32_t*>(&hp);
    float r0 = (v0 - __half2float(h0)) * RSCALE;
    float r1 = (v1 - __half2float(h1)) * RSCALE;
    __half2 lp = __floats2half2_rn(r0, r1);
    lo = *reinterpret_cast<uint32_t*>(&lp);
}

__global__ void __launch_bounds__(NTHREADS)
router_main_kernel(const float* __restrict__ x,
                   const float* __restrict__ W,
                   const float* __restrict__ b,
                   float* __restrict__ out, int N)
{
    __shared__ float sm[SMEM_FLOATS];
    __shared__ int is_last;
    uint32_t* su = reinterpret_cast<uint32_t*>(sm);
    const int tid  = threadIdx.x;
    const int lane = tid & 31;
    const int wid  = tid >> 5;          // 0..7: tokens [16*wid, +16)
    const int g    = lane >> 2;         // 0..7
    const int tg   = lane & 3;          // 0..3
    const int row0 = blockIdx.x * BM;

    float sum[8][4];     // FFMA-maintained hh sums (unbiased)
    float acc[8][4];     // TC hh accumulator, drained each chunk
    float cor[8][4];     // TC correction accumulator (scaled by RSCALE)
    #pragma unroll
    for (int nf = 0; nf < 8; nf++)
        #pragma unroll
        for (int i = 0; i < 4; i++) {
            sum[nf][i] = 0.0f; acc[nf][i] = 0.0f; cor[nf][i] = 0.0f;
        }

    // ---- prefetch chunk 0 ----
    float4 a4[4]; float bw0[4], bw1[4];
    {
        const float* xp = x + (size_t)row0 * DDIM;
        #pragma unroll
        for (int j = 0; j < 4; j++) {
            int idx = tid + j * NTHREADS;
            a4[j] = *(const float4*)(xp + (size_t)(idx >> 3) * DDIM + ((idx & 7) << 2));
        }
        #pragma unroll
        for (int j = 0; j < 4; j++) {
            int pp = tid + j * NTHREADS;
            int p = pp >> 6, e = pp & 63;
            bw0[j] = W[(size_t)(2 * p) * EDIM + e];
            bw1[j] = W[(size_t)(2 * p + 1) * EDIM + e];
        }
    }

    for (int c = 0; c < NCHUNK; c++) {
        // ---- stage chunk c: A raw floats; B split to BH/BL u32 tiles ----
        #pragma unroll
        for (int j = 0; j < 4; j++) {
            int idx = tid + j * NTHREADS;
            *(float4*)(sm + A_OFF + (idx >> 3) * ASTRIDE + ((idx & 7) << 2)) = a4[j];
        }
        #pragma unroll
        for (int j = 0; j < 4; j++) {
            int pp = tid + j * NTHREADS;
            int p = pp >> 6, e = pp & 63;
            uint32_t h, l;
            prep2(bw0[j], bw1[j], h, l);
            su[BH_U + p * BPITCH + e] = h;
            su[BL_U + p * BPITCH + e] = l;
        }
        __syncthreads();

        // ---- issue global loads for chunk c+1 (overlap with MMAs) ----
        if (c + 1 < NCHUNK) {
            const int k0 = (c + 1) * BK;
            const float* xp = x + (size_t)row0 * DDIM + k0;
            #pragma unroll
            for (int j = 0; j < 4; j++) {
                int idx = tid + j * NTHREADS;
                a4[j] = *(const float4*)(xp + (size_t)(idx >> 3) * DDIM + ((idx & 7) << 2));
            }
            #pragma unroll
            for (int j = 0; j < 4; j++) {
                int pp = tid + j * NTHREADS;
                int p = pp >> 6, e = pp & 63;
                bw0[j] = W[(size_t)(k0 + 2 * p) * EDIM + e];
                bw1[j] = W[(size_t)(k0 + 2 * p + 1) * EDIM + e];
            }
        }

        // ---- compute chunk c: two k16 halves ----
        #pragma unroll
        for (int j = 0; j < 2; j++) {
            const int pb = (j << 3) + tg;
            const int kb = (j << 4) + (tg << 1);

            int r0 = (wid << 4) + g;
            int r1 = r0 + 8;
            float2 p0 = *(const float2*)(sm + A_OFF + r0 * ASTRIDE + kb);
            float2 p1 = *(const float2*)(sm + A_OFF + r1 * ASTRIDE + kb);
            float2 p2 = *(const float2*)(sm + A_OFF + r0 * ASTRIDE + kb + 8);
            float2 p3 = *(const float2*)(sm + A_OFF + r1 * ASTRIDE + kb + 8);
            uint32_t ah0, ah1, ah2, ah3, al0, al1, al2, al3;
            prep2(p0.x, p0.y, ah0, al0);
            prep2(p1.x, p1.y, ah1, al1);
            prep2(p2.x, p2.y, ah2, al2);
            prep2(p3.x, p3.y, ah3, al3);

            #pragma unroll
            for (int nf = 0; nf < 8; nf++) {
                int e = (nf << 3) + g;
                uint32_t bh0 = su[BH_U + pb * BPITCH + e];
                uint32_t bh1 = su[BH_U + (pb + 4) * BPITCH + e];
                uint32_t bl0 = su[BL_U + pb * BPITCH + e];
                uint32_t bl1 = su[BL_U + (pb + 4) * BPITCH + e];
                mma16h(acc[nf], ah0, ah1, ah2, ah3, bh0, bh1);
                mma16h(cor[nf], ah0, ah1, ah2, ah3, bl0, bl1);
                mma16h(cor[nf], al0, al1, al2, al3, bh0, bh1);
            }
        }

        // ---- drain hh accumulator into FFMA sums ----
        #pragma unroll
        for (int nf = 0; nf < 8; nf++)
            #pragma unroll
            for (int i = 0; i < 4; i++) {
                sum[nf][i] += acc[nf][i];
                acc[nf][i] = 0.0f;
            }

        __syncthreads();
    }

    // ---- bias/cnt init ----
    if (tid < EDIM) {
        sm[BIAS_OFF + tid] = b[tid];
        ((int*)sm)[CNT_OFF + tid] = 0;
    }

    // ---- spill logits (sum + unscaled correction) to smem ----
    {
        float* lg = sm + LG_OFF;
        int t = (wid << 4) + g;
        #pragma unroll
        for (int nf = 0; nf < 8; nf++) {
            int e = (nf << 3) + (tg << 1);
            lg[t * LG_STRIDE + e]           = sum[nf][0] + cor[nf][0] * RSCALE_I;
            lg[t * LG_STRIDE + e + 1]       = sum[nf][1] + cor[nf][1] * RSCALE_I;
            lg[(t + 8) * LG_STRIDE + e]     = sum[nf][2] + cor[nf][2] * RSCALE_I;
            lg[(t + 8) * LG_STRIDE + e + 1] = sum[nf][3] + cor[nf][3] * RSCALE_I;
        }
    }
    __syncthreads();

    // ---- per-token: bias + top-2 + softmax + outputs ----
    if (tid < BM) {
        const int m = tid;
        float lg[EDIM];
        #pragma unroll
        for (int e = 0; e < EDIM; e++)
            lg[e] = sm[LG_OFF + m * LG_STRIDE + e] + sm[BIAS_OFF + e];

        float v1 = -3.0e38f, v2 = -3.0e38f;
        int i1 = 0, i2 = 0;
        #pragma unroll
        for (int e = 0; e < EDIM; e++) {
            float l = lg[e];
            if (l > v1)      { v2 = v1; i2 = i1; v1 = l; i1 = e; }
            else if (l > v2) { v2 = l; i2 = e; }
        }
        float s = 0.0f;
        #pragma unroll
        for (int e = 0; e < EDIM; e++) s += __expf(lg[e] - v1);
        float inv = 1.0f / s;

        int gt = row0 + m;
        out[2 * gt + 0] = inv;
        out[2 * gt + 1] = __expf(v2 - v1) * inv;
        float* oi = out + 2 * (size_t)N;
        oi[2 * gt + 0] = (float)i1;
        oi[2 * gt + 1] = (float)i2;

        atomicAdd((int*)sm + CNT_OFF + i1, 1);
        atomicAdd((int*)sm + CNT_OFF + i2, 1);

        #pragma unroll
        for (int e = 0; e < EDIM; e++)
            sm[LG_OFF + m * LG_STRIDE + e] = __expf(lg[e] - v1) * inv;
    }
    __syncthreads();

    // ---- per-expert prob sums + global accumulation ----
    if (tid < EDIM) {
        float s = 0.0f;
        #pragma unroll 8
        for (int m = 0; m < BM; m++)
            s += sm[LG_OFF + m * LG_STRIDE + tid];
        atomicAdd(&g_prob[tid], s);
        atomicAdd(&g_cnt[tid], (float)(((int*)sm)[CNT_OFF + tid]));
        __threadfence();   // make this block's adds globally visible (release)
    }
    __syncthreads();

    // ---- last-block finalize (threadfence reduction) ----
    if (tid == 0) {
        unsigned old = atomicAdd(&g_done, 1u);
        is_last = (old == (unsigned)(gridDim.x - 1)) ? 1 : 0;
    }
    __syncthreads();
    if (is_last) {
        __threadfence();   // acquire side
        if (tid < EDIM) {
            float cv = *(volatile float*)&g_cnt[tid];
            float pv = *(volatile float*)&g_prob[tid];
            float invN = 1.0f / (float)N;
            sm[BIAS_OFF + tid] = (cv * invN) * (pv * invN);
        }
        __syncthreads();
        if (tid < 32) {
            float s = sm[BIAS_OFF + tid] + sm[BIAS_OFF + tid + 32];
            #pragma unroll
            for (int o = 16; o > 0; o >>= 1)
                s += __shfl_down_sync(0xffffffffu, s, o);
            if (tid == 0) out[4 * (size_t)N] = (float)EDIM * s;
        }
    }
}

extern "C" void kernel_launch(void* const* d_in, const int* in_sizes, int n_in,
                              void* d_out, int out_size) {
    const float* x = (const float*)d_in[0];
    const float* W = (const float*)d_in[1];
    const float* b = (const float*)d_in[2];
    int N = in_sizes[0] / DDIM;   // 16384

    float* out = (float*)d_out;
    zero_acc_kernel<<<1, 64>>>();
    router_main_kernel<<<N / BM, NTHREADS>>>(x, W, b, out, N);
}